// round 10
// baseline (speedup 1.0000x reference)
#include <cuda_runtime.h>
#include <cuda_bf16.h>
#include <cuda_fp16.h>
#include <math.h>
#include <stdint.h>

#define N_NODES 100000
#define E_EDGES 3200000
#define F 256
#define NOUT 128

#define SCAN_BLK 256
#define SCAN_NBLK ((N_NODES + SCAN_BLK - 1) / SCAN_BLK)   // 391

// ---------------- scratch (device globals; no allocation allowed) ----------
__device__ __half g_Sh[N_NODES * F]; // support = x @ W_nb (fp16 for cheap gather)
__device__ float g_A [N_NODES * F];  // x@W_self + b (GEMM output, SpMM base)
__device__ float g_X1[N_NODES * F];  // x after layer-1 relu
__device__ float g_g1[N_NODES];
__device__ float g_g2[N_NODES];
__device__ float g_part[512 * 4];
__device__ float g_stat[4];
__device__ float g_colsum[F];

// transposed + split weights: [wid][n*256+k], wid: 0=self1 1=nb1 2=self2 3=nb2
__device__ __nv_bfloat16 g_Wt1[4 * F * F];
__device__ __nv_bfloat16 g_Wt2[4 * F * F];

// CSR scratch
__device__ int   g_cnt[N_NODES];
__device__ int   g_rowptr[N_NODES + 1];
__device__ int   g_bsum[SCAN_NBLK];
__device__ int   g_boff[SCAN_NBLK];
__device__ int2  g_csr[E_EDGES];     // (col, val-bits) packed: one LDG.64/edge

#define NEG_BIG (-3.0e38f)
#define SMEM_SWIZZLE_128B(o) ((o) ^ (((o) >> 3) & 0x70))

__device__ __forceinline__ uint32_t smem_u32(const void* p) {
    uint32_t a;
    asm("{ .reg .u64 t; cvta.to.shared.u64 t, %1; cvt.u32.u64 %0, t; }"
        : "=r"(a) : "l"(p));
    return a;
}

__device__ __forceinline__ void ldmatrix_x4(uint32_t* r, uint32_t addr) {
    asm volatile("ldmatrix.sync.aligned.m8n8.x4.shared.b16 {%0,%1,%2,%3}, [%4];"
        : "=r"(r[0]), "=r"(r[1]), "=r"(r[2]), "=r"(r[3]) : "r"(addr));
}

__device__ __forceinline__ void mma_bf16(float* d, const uint32_t* a, const uint32_t* b) {
    asm volatile(
        "mma.sync.aligned.m16n8k16.row.col.f32.bf16.bf16.f32 "
        "{%0,%1,%2,%3}, {%4,%5,%6,%7}, {%8,%9}, {%0,%1,%2,%3};"
        : "+f"(d[0]), "+f"(d[1]), "+f"(d[2]), "+f"(d[3])
        : "r"(a[0]), "r"(a[1]), "r"(a[2]), "r"(a[3]), "r"(b[0]), "r"(b[1]));
}

// ---------------- init: zero cnt + colsum in one kernel ----------------
__global__ void k_zero_init() {
    int i = blockIdx.x * blockDim.x + threadIdx.x;
    if (i < N_NODES) g_cnt[i] = 0;
    if (i < F) g_colsum[i] = 0.0f;
}

// ---------------- CSR build ------------------------------------------------
__global__ void k_hist(const int* __restrict__ er) {
    int i = blockIdx.x * blockDim.x + threadIdx.x;
    if (i < E_EDGES) atomicAdd(&g_cnt[er[i]], 1);
}

__device__ __forceinline__ int warp_scan_incl(int v, int lane) {
    #pragma unroll
    for (int off = 1; off < 32; off <<= 1) {
        int t = __shfl_up_sync(0xffffffffu, v, off);
        if (lane >= off) v += t;
    }
    return v;
}

__global__ void k_scan1() {
    __shared__ int wsum[8];
    int t = threadIdx.x;
    int lane = t & 31, wid = t >> 5;
    int i = blockIdx.x * SCAN_BLK + t;
    int v = (i < N_NODES) ? g_cnt[i] : 0;
    int incl = warp_scan_incl(v, lane);
    if (lane == 31) wsum[wid] = incl;
    __syncthreads();
    if (wid == 0) {
        int s = (lane < 8) ? wsum[lane] : 0;
        s = warp_scan_incl(s, lane);
        if (lane < 8) wsum[lane] = s;
    }
    __syncthreads();
    int off = wid ? wsum[wid - 1] : 0;
    incl += off;
    if (i < N_NODES) g_rowptr[i] = incl - v;
    if (t == SCAN_BLK - 1) g_bsum[blockIdx.x] = incl;
}

__global__ void k_scan2() {
    __shared__ int wsum[16];
    int t = threadIdx.x;
    int lane = t & 31, wid = t >> 5;
    int v = (t < SCAN_NBLK) ? g_bsum[t] : 0;
    int incl = warp_scan_incl(v, lane);
    if (lane == 31) wsum[wid] = incl;
    __syncthreads();
    if (wid == 0) {
        int s = (lane < 16) ? wsum[lane] : 0;
        s = warp_scan_incl(s, lane);
        if (lane < 16) wsum[lane] = s;
    }
    __syncthreads();
    int off = wid ? wsum[wid - 1] : 0;
    incl += off;
    if (t < SCAN_NBLK) g_boff[t] = incl - v;
}

__global__ void k_scan3() {
    int i = blockIdx.x * blockDim.x + threadIdx.x;
    if (i < N_NODES) {
        int val = g_rowptr[i] + g_boff[i >> 8];
        g_rowptr[i] = val;
        g_cnt[i] = val;
    }
    if (i == 0) g_rowptr[N_NODES] = E_EDGES;
}

__global__ void k_scatter(const int* __restrict__ er, const int* __restrict__ ec,
                          const float* __restrict__ ev) {
    int i = blockIdx.x * blockDim.x + threadIdx.x;
    if (i < E_EDGES) {
        int row = er[i];
        int pos = atomicAdd(&g_cnt[row], 1);
        g_csr[pos] = make_int2(ec[i], __float_as_int(ev[i]));
    }
}

// ---------------- weight transpose + bf16 split (all 4 in one) -------------
__global__ void k_wsplit_all(const float* __restrict__ W0, const float* __restrict__ W1,
                             const float* __restrict__ W2, const float* __restrict__ W3)
{
    int i = blockIdx.x * blockDim.x + threadIdx.x;
    if (i >= F * F) return;
    int w = blockIdx.y;
    const float* W = (w == 0) ? W0 : (w == 1) ? W1 : (w == 2) ? W2 : W3;
    int n = i >> 8, k = i & 255;
    float x = W[k * F + n];
    __nv_bfloat16 h = __float2bfloat16(x);
    g_Wt1[w * F * F + i] = h;
    g_Wt2[w * F * F + i] = __float2bfloat16(x - __bfloat162float(h));
}

// ---------------- fused-split mma.sync dual GEMM ---------------------------
// gvec != null: row scale r = exp(gvec[row]-g_stat[0]) / g_stat[1]
__global__ __launch_bounds__(256, 2) void k_gemm_fused(
    const float* __restrict__ Asrc, const float* __restrict__ gvec,
    const __nv_bfloat16* __restrict__ Ws1, const __nv_bfloat16* __restrict__ Ws2,
    const __nv_bfloat16* __restrict__ Wn1, const __nv_bfloat16* __restrict__ Wn2,
    const float* __restrict__ bias,
    float* __restrict__ Cs, __half* __restrict__ Sn, int M)
{
    extern __shared__ __align__(16) char smem[];

    const int tid  = threadIdx.x;
    const int wid  = tid >> 5;
    const int lane = tid & 31;
    const int rowBlock = blockIdx.x * 128;
    const int nBlock   = blockIdx.y * 64;
    const int grp = wid >> 2;            // 0 = self, 1 = nb
    const int wm  = (wid & 3) * 32;

    const uint32_t sA1u = smem_u32(smem);
    const uint32_t sA2u = sA1u + 16384;
    const uint32_t B1u  = sA1u + 32768 + (grp ? 8192 : 0);
    const uint32_t B2u  = sA1u + 49152 + (grp ? 8192 : 0);

    float st0 = 0.f, inv_s = 1.f;
    if (gvec) { st0 = g_stat[0]; inv_s = 1.0f / g_stat[1]; }

    float acc[2][8][4];
    #pragma unroll
    for (int mi = 0; mi < 2; mi++)
        #pragma unroll
        for (int ni = 0; ni < 8; ni++)
            #pragma unroll
            for (int q = 0; q < 4; q++) acc[mi][ni][q] = 0.0f;

    const int aRow = (lane & 15);
    const int aKc  = (lane >> 4) << 3;
    const int bN   = ((lane >> 4) & 1) * 8 + (lane & 7);
    const int bKc  = ((lane >> 3) & 1) * 8;

    #pragma unroll 1
    for (int k0 = 0; k0 < F; k0 += 64) {
        #pragma unroll
        for (int it = 0; it < 8; it++) {
            int idx = tid + it * 256;
            int r   = idx >> 4;
            int c4  = idx & 15;
            int grow = rowBlock + r;
            float4 v = make_float4(0.f, 0.f, 0.f, 0.f);
            if (grow < M) {
                v = *reinterpret_cast<const float4*>(Asrc + (size_t)grow * F + k0 + c4 * 4);
                if (gvec) {
                    float rr = __expf(gvec[grow] - st0) * inv_s;
                    v.x *= rr; v.y *= rr; v.z *= rr; v.w *= rr;
                }
            }
            __nv_bfloat162 h01 = __floats2bfloat162_rn(v.x, v.y);
            __nv_bfloat162 h23 = __floats2bfloat162_rn(v.z, v.w);
            float2 f01 = __bfloat1622float2(h01);
            float2 f23 = __bfloat1622float2(h23);
            __nv_bfloat162 l01 = __floats2bfloat162_rn(v.x - f01.x, v.y - f01.y);
            __nv_bfloat162 l23 = __floats2bfloat162_rn(v.z - f23.x, v.w - f23.y);
            uint32_t off = SMEM_SWIZZLE_128B((uint32_t)(r * 128 + c4 * 8));
            uint2 hi, lo;
            hi.x = *reinterpret_cast<uint32_t*>(&h01);
            hi.y = *reinterpret_cast<uint32_t*>(&h23);
            lo.x = *reinterpret_cast<uint32_t*>(&l01);
            lo.y = *reinterpret_cast<uint32_t*>(&l23);
            *reinterpret_cast<uint2*>(smem + off)         = hi;
            *reinterpret_cast<uint2*>(smem + 16384 + off) = lo;
        }
        #pragma unroll
        for (int t = 0; t < 4; t++) {
            const __nv_bfloat16* Wp = (t == 0) ? Ws1 : (t == 1) ? Wn1 : (t == 2) ? Ws2 : Wn2;
            char* dst = smem + 32768 + t * 8192;
            #pragma unroll
            for (int it = 0; it < 2; it++) {
                int idx = tid + it * 256;
                int r = idx >> 3, c = idx & 7;
                uint32_t off = SMEM_SWIZZLE_128B((uint32_t)(r * 128 + c * 16));
                *reinterpret_cast<uint4*>(dst + off) =
                    *reinterpret_cast<const uint4*>(Wp + (size_t)(nBlock + r) * F + k0 + c * 8);
            }
        }
        __syncthreads();

        #pragma unroll 1
        for (int combo = 0; combo < 3; combo++) {
            const uint32_t Au = (combo == 1) ? sA2u : sA1u;
            const uint32_t Bu = (combo == 2) ? B2u  : B1u;
            #pragma unroll
            for (int kk = 0; kk < 64; kk += 16) {
                uint32_t a[2][4];
                #pragma unroll
                for (int mi = 0; mi < 2; mi++) {
                    int row = wm + mi * 16 + aRow;
                    ldmatrix_x4(a[mi], Au +
                        SMEM_SWIZZLE_128B((uint32_t)(row * 128 + (kk + aKc) * 2)));
                }
                uint32_t b[8][2];
                #pragma unroll
                for (int np = 0; np < 4; np++) {
                    uint32_t r4[4];
                    int n = np * 16 + bN;
                    ldmatrix_x4(r4, Bu +
                        SMEM_SWIZZLE_128B((uint32_t)(n * 128 + (kk + bKc) * 2)));
                    b[np * 2][0]     = r4[0];
                    b[np * 2][1]     = r4[1];
                    b[np * 2 + 1][0] = r4[2];
                    b[np * 2 + 1][1] = r4[3];
                }
                #pragma unroll
                for (int mi = 0; mi < 2; mi++)
                    #pragma unroll
                    for (int ni = 0; ni < 8; ni++)
                        mma_bf16(acc[mi][ni], a[mi], b[ni]);
            }
        }
        __syncthreads();
    }

    const int rq = lane >> 2;
    const int cq = (lane & 3) * 2;
    if (grp == 0) {
        #pragma unroll
        for (int mi = 0; mi < 2; mi++) {
            #pragma unroll
            for (int ni = 0; ni < 8; ni++) {
                int n = nBlock + ni * 8 + cq;
                float b0 = bias[n], b1 = bias[n + 1];
                int m0 = rowBlock + wm + mi * 16 + rq;
                if (m0 < M)
                    *reinterpret_cast<float2*>(Cs + (size_t)m0 * F + n) =
                        make_float2(acc[mi][ni][0] + b0, acc[mi][ni][1] + b1);
                int m1 = m0 + 8;
                if (m1 < M)
                    *reinterpret_cast<float2*>(Cs + (size_t)m1 * F + n) =
                        make_float2(acc[mi][ni][2] + b0, acc[mi][ni][3] + b1);
            }
        }
    } else {
        #pragma unroll
        for (int mi = 0; mi < 2; mi++) {
            #pragma unroll
            for (int ni = 0; ni < 8; ni++) {
                int n = nBlock + ni * 8 + cq;
                int m0 = rowBlock + wm + mi * 16 + rq;
                if (m0 < M)
                    *reinterpret_cast<__half2*>(Sn + (size_t)m0 * F + n) =
                        __floats2half2_rn(acc[mi][ni][0], acc[mi][ni][1]);
                int m1 = m0 + 8;
                if (m1 < M)
                    *reinterpret_cast<__half2*>(Sn + (size_t)m1 * F + n) =
                        __floats2half2_rn(acc[mi][ni][2], acc[mi][ni][3]);
            }
        }
    }
}

// ---------------- shared SpMM edge-gather core -----------------------------
__device__ __forceinline__ void spmm_row(int s, int e, int lane, float* acc)
{
    const uint4* Sv = reinterpret_cast<const uint4*>(g_Sh);
    #pragma unroll
    for (int j = 0; j < 8; j++) acc[j] = 0.f;

    int i = s;
    for (; i + 3 < e; i += 4) {
        int2 e0 = g_csr[i],     e1 = g_csr[i + 1];
        int2 e2 = g_csr[i + 2], e3 = g_csr[i + 3];
        float v0 = __int_as_float(e0.y), v1 = __int_as_float(e1.y);
        float v2 = __int_as_float(e2.y), v3 = __int_as_float(e3.y);
        uint4 q0 = __ldg(Sv + (size_t)e0.x * 32 + lane);
        uint4 q1 = __ldg(Sv + (size_t)e1.x * 32 + lane);
        uint4 q2 = __ldg(Sv + (size_t)e2.x * 32 + lane);
        uint4 q3 = __ldg(Sv + (size_t)e3.x * 32 + lane);
        const __half2* h0 = reinterpret_cast<const __half2*>(&q0);
        const __half2* h1 = reinterpret_cast<const __half2*>(&q1);
        const __half2* h2 = reinterpret_cast<const __half2*>(&q2);
        const __half2* h3 = reinterpret_cast<const __half2*>(&q3);
        #pragma unroll
        for (int j = 0; j < 4; j++) {
            float2 f0 = __half22float2(h0[j]);
            float2 f1 = __half22float2(h1[j]);
            float2 f2 = __half22float2(h2[j]);
            float2 f3 = __half22float2(h3[j]);
            acc[2 * j]     += v0 * f0.x + v1 * f1.x + v2 * f2.x + v3 * f3.x;
            acc[2 * j + 1] += v0 * f0.y + v1 * f1.y + v2 * f2.y + v3 * f3.y;
        }
    }
    for (; i < e; i++) {
        int2 e0 = g_csr[i];
        float v0 = __int_as_float(e0.y);
        uint4 q0 = __ldg(Sv + (size_t)e0.x * 32 + lane);
        const __half2* h0 = reinterpret_cast<const __half2*>(&q0);
        #pragma unroll
        for (int j = 0; j < 4; j++) {
            float2 f0 = __half22float2(h0[j]);
            acc[2 * j]     += v0 * f0.x;
            acc[2 * j + 1] += v0 * f0.y;
        }
    }
}

// ---------------- SpMM-1 fused: relu -> X1 + gate dots ---------------------
__global__ __launch_bounds__(256) void k_spmm1(
    const float* __restrict__ w1, const float* __restrict__ b1g,
    const float* __restrict__ w2, const float* __restrict__ b2g)
{
    int warp = (blockIdx.x * blockDim.x + threadIdx.x) >> 5;
    int lane = threadIdx.x & 31;
    if (warp >= N_NODES) return;

    float acc[8];
    spmm_row(g_rowptr[warp], g_rowptr[warp + 1], lane, acc);

    const float* Ap = g_A + (size_t)warp * F + lane * 8;
    float4 b0 = *reinterpret_cast<const float4*>(Ap);
    float4 b1 = *reinterpret_cast<const float4*>(Ap + 4);
    float x[8];
    x[0] = fmaxf(b0.x + acc[0], 0.f); x[1] = fmaxf(b0.y + acc[1], 0.f);
    x[2] = fmaxf(b0.z + acc[2], 0.f); x[3] = fmaxf(b0.w + acc[3], 0.f);
    x[4] = fmaxf(b1.x + acc[4], 0.f); x[5] = fmaxf(b1.y + acc[5], 0.f);
    x[6] = fmaxf(b1.z + acc[6], 0.f); x[7] = fmaxf(b1.w + acc[7], 0.f);

    float* Xp = g_X1 + (size_t)warp * F + lane * 8;
    *reinterpret_cast<float4*>(Xp)     = make_float4(x[0], x[1], x[2], x[3]);
    *reinterpret_cast<float4*>(Xp + 4) = make_float4(x[4], x[5], x[6], x[7]);

    float4 u0 = __ldg(reinterpret_cast<const float4*>(w1 + lane * 8));
    float4 u1 = __ldg(reinterpret_cast<const float4*>(w1 + lane * 8 + 4));
    float4 t0 = __ldg(reinterpret_cast<const float4*>(w2 + lane * 8));
    float4 t1 = __ldg(reinterpret_cast<const float4*>(w2 + lane * 8 + 4));
    float d1 = x[0]*u0.x + x[1]*u0.y + x[2]*u0.z + x[3]*u0.w
             + x[4]*u1.x + x[5]*u1.y + x[6]*u1.z + x[7]*u1.w;
    float d2 = x[0]*t0.x + x[1]*t0.y + x[2]*t0.z + x[3]*t0.w
             + x[4]*t1.x + x[5]*t1.y + x[6]*t1.z + x[7]*t1.w;
    #pragma unroll
    for (int off = 16; off; off >>= 1) {
        d1 += __shfl_xor_sync(0xffffffffu, d1, off);
        d2 += __shfl_xor_sync(0xffffffffu, d2, off);
    }
    if (lane == 0) {
        g_g1[warp] = d1 + b1g[0];
        g_g2[warp] = d2 + b2g[0];
    }
}

// ---------------- SpMM-2 fused: relu, mix (z on the fly), out, colsum ------
#define SPMM2_BLOCKS 1600
__global__ __launch_bounds__(256) void k_spmm2(float* __restrict__ out)
{
    __shared__ float cs[F];
    int tid  = threadIdx.x;
    int lane = tid & 31;
    if (tid < F) cs[tid] = 0.f;
    __syncthreads();

    const float st2   = g_stat[2];
    const float inv_s = 1.0f / g_stat[3];

    float local[8];
    #pragma unroll
    for (int j = 0; j < 8; j++) local[j] = 0.f;

    int warpG  = (blockIdx.x * blockDim.x + tid) >> 5;
    int nWarps = SPMM2_BLOCKS * (256 / 32);

    for (int row = warpG; row < N_NODES; row += nWarps) {
        float acc[8];
        spmm_row(g_rowptr[row], g_rowptr[row + 1], lane, acc);

        const float* Ap = g_A + (size_t)row * F + lane * 8;
        float4 b0 = *reinterpret_cast<const float4*>(Ap);
        float4 b1 = *reinterpret_cast<const float4*>(Ap + 4);
        float x2[8];
        x2[0] = fmaxf(b0.x + acc[0], 0.f); x2[1] = fmaxf(b0.y + acc[1], 0.f);
        x2[2] = fmaxf(b0.z + acc[2], 0.f); x2[3] = fmaxf(b0.w + acc[3], 0.f);
        x2[4] = fmaxf(b1.x + acc[4], 0.f); x2[5] = fmaxf(b1.y + acc[5], 0.f);
        x2[6] = fmaxf(b1.z + acc[6], 0.f); x2[7] = fmaxf(b1.w + acc[7], 0.f);

        float z  = __expf(g_g2[row] - st2) * inv_s;
        float iz = 1.f - z;
        const float* Xp = g_X1 + (size_t)row * F + lane * 8;
        float4 x10 = *reinterpret_cast<const float4*>(Xp);
        float4 x11 = *reinterpret_cast<const float4*>(Xp + 4);
        float xe[8];
        xe[0] = iz * x10.x + z * x2[0]; xe[1] = iz * x10.y + z * x2[1];
        xe[2] = iz * x10.z + z * x2[2]; xe[3] = iz * x10.w + z * x2[3];
        xe[4] = iz * x11.x + z * x2[4]; xe[5] = iz * x11.y + z * x2[5];
        xe[6] = iz * x11.z + z * x2[6]; xe[7] = iz * x11.w + z * x2[7];

        float* Op = out + (size_t)row * F + lane * 8;
        *reinterpret_cast<float4*>(Op)     = make_float4(xe[0], xe[1], xe[2], xe[3]);
        *reinterpret_cast<float4*>(Op + 4) = make_float4(xe[4], xe[5], xe[6], xe[7]);

        #pragma unroll
        for (int j = 0; j < 8; j++) local[j] += xe[j];
    }

    #pragma unroll
    for (int j = 0; j < 8; j++)
        atomicAdd(&cs[lane * 8 + j], local[j]);
    __syncthreads();
    if (tid < F) atomicAdd(&g_colsum[tid], cs[tid]);
}

// ---------------- softmax over nodes: online (max, sumexp) -----------------
__device__ __forceinline__ void merge_ms(float& m, float& s, float mb, float sb) {
    float M = fmaxf(m, mb);
    s = s * __expf(m - M) + sb * __expf(mb - M);
    m = M;
}

__global__ void k_softmax_part()
{
    float m1 = NEG_BIG, s1 = 0.f, m2 = NEG_BIG, s2 = 0.f;
    for (int i = blockIdx.x * blockDim.x + threadIdx.x; i < N_NODES;
         i += gridDim.x * blockDim.x) {
        float v1 = g_g1[i];
        merge_ms(m1, s1, v1, 1.0f);
        float v2 = g_g2[i];
        merge_ms(m2, s2, v2, 1.0f);
    }
    __shared__ float sm1[256], ss1[256], sm2[256], ss2[256];
    int t = threadIdx.x;
    sm1[t] = m1; ss1[t] = s1; sm2[t] = m2; ss2[t] = s2;
    __syncthreads();
    for (int off = 128; off; off >>= 1) {
        if (t < off) {
            float mm = sm1[t], ss = ss1[t];
            merge_ms(mm, ss, sm1[t + off], ss1[t + off]);
            sm1[t] = mm; ss1[t] = ss;
            mm = sm2[t]; ss = ss2[t];
            merge_ms(mm, ss, sm2[t + off], ss2[t + off]);
            sm2[t] = mm; ss2[t] = ss;
        }
        __syncthreads();
    }
    if (t == 0) {
        g_part[blockIdx.x * 4 + 0] = sm1[0];
        g_part[blockIdx.x * 4 + 1] = ss1[0];
        g_part[blockIdx.x * 4 + 2] = sm2[0];
        g_part[blockIdx.x * 4 + 3] = ss2[0];
    }
}

__global__ void k_softmax_final(int nparts)
{
    __shared__ float sm1[128], ss1[128], sm2[128], ss2[128];
    int t = threadIdx.x;
    float m1 = NEG_BIG, s1 = 0.f, m2 = NEG_BIG, s2 = 0.f;
    if (t < nparts) {
        m1 = g_part[t * 4 + 0]; s1 = g_part[t * 4 + 1];
        m2 = g_part[t * 4 + 2]; s2 = g_part[t * 4 + 3];
    }
    sm1[t] = m1; ss1[t] = s1; sm2[t] = m2; ss2[t] = s2;
    __syncthreads();
    for (int off = 64; off; off >>= 1) {
        if (t < off) {
            float mm = sm1[t], ss = ss1[t];
            merge_ms(mm, ss, sm1[t + off], ss1[t + off]);
            sm1[t] = mm; ss1[t] = ss;
            mm = sm2[t]; ss = ss2[t];
            merge_ms(mm, ss, sm2[t + off], ss2[t + off]);
            sm2[t] = mm; ss2[t] = ss;
        }
        __syncthreads();
    }
    if (t == 0) {
        g_stat[0] = sm1[0]; g_stat[1] = ss1[0];
        g_stat[2] = sm2[0]; g_stat[3] = ss2[0];
    }
}

// ---------------- output head ---------------------------------------------
__global__ void k_out(const float* __restrict__ e2pw, const float* __restrict__ e2pb,
                      float* __restrict__ out)
{
    __shared__ float mean[F];
    for (int i = threadIdx.x; i < F; i += blockDim.x)
        mean[i] = g_colsum[i] * (1.0f / N_NODES);
    __syncthreads();
    int j = threadIdx.x;
    if (j < NOUT) {
        float acc = e2pb[j];
        #pragma unroll 8
        for (int k = 0; k < F; k++)
            acc += mean[k] * e2pw[(size_t)k * NOUT + j];
        out[(size_t)N_NODES * F + j] = acc;
    }
}

// ---------------- launch ----------------
extern "C" void kernel_launch(void* const* d_in, const int* in_sizes, int n_in,
                              void* d_out, int out_size)
{
    const float* inputs  = (const float*)d_in[0];
    const int*   er      = (const int*)  d_in[1];
    const int*   ec      = (const int*)  d_in[2];
    const float* ev      = (const float*)d_in[3];
    const float* W_self1 = (const float*)d_in[4];
    const float* W_nb1   = (const float*)d_in[5];
    const float* b1      = (const float*)d_in[6];
    const float* W_self2 = (const float*)d_in[7];
    const float* W_nb2   = (const float*)d_in[8];
    const float* b2      = (const float*)d_in[9];
    const float* g1w     = (const float*)d_in[10];
    const float* g1b     = (const float*)d_in[11];
    const float* g2w     = (const float*)d_in[12];
    const float* g2b     = (const float*)d_in[13];
    const float* e2pw    = (const float*)d_in[14];
    const float* e2pb    = (const float*)d_in[15];
    float* out = (float*)d_out;

    float *pA, *pX1, *pG1;
    __half* pSh;
    cudaGetSymbolAddress((void**)&pA,  g_A);
    cudaGetSymbolAddress((void**)&pX1, g_X1);
    cudaGetSymbolAddress((void**)&pG1, g_g1);
    cudaGetSymbolAddress((void**)&pSh, g_Sh);
    __nv_bfloat16 *pWt1, *pWt2;
    cudaGetSymbolAddress((void**)&pWt1, g_Wt1);
    cudaGetSymbolAddress((void**)&pWt2, g_Wt2);

    const int SMEM_GEMM = 65536;
    cudaFuncSetAttribute(k_gemm_fused, cudaFuncAttributeMaxDynamicSharedMemorySize, SMEM_GEMM);

    const int EB = (E_EDGES + 255) / 256;
    const int NB = (N_NODES + 255) / 256;
    dim3 gmm((N_NODES + 127) / 128, 4);
    dim3 gws((F * F + 255) / 256, 4);

    // ---- CSR build + init (serial — overlap regressed in R9) ----
    k_zero_init<<<NB, 256>>>();
    k_hist<<<EB, 256>>>(er);
    k_scan1<<<SCAN_NBLK, SCAN_BLK>>>();
    k_scan2<<<1, 512>>>();
    k_scan3<<<NB, 256>>>();
    k_scatter<<<EB, 256>>>(er, ec, ev);

    // ---- weight prep ----
    k_wsplit_all<<<gws, 256>>>(W_self1, W_nb1, W_self2, W_nb2);

    // ---- layer 1 ----
    k_gemm_fused<<<gmm, 256, SMEM_GEMM>>>(inputs, nullptr,
                             pWt1 + 0 * F * F, pWt2 + 0 * F * F,
                             pWt1 + 1 * F * F, pWt2 + 1 * F * F,
                             b1, pA, pSh, N_NODES);
    k_spmm1<<<(N_NODES * 32 + 255) / 256, 256>>>(g1w, g1b, g2w, g2b);

    // ---- softmax gates over nodes ----
    k_softmax_part<<<120, 256>>>();
    k_softmax_final<<<1, 128>>>(120);

    // ---- layer 2 (r computed in-GEMM from g1 + stats) ----
    k_gemm_fused<<<gmm, 256, SMEM_GEMM>>>(pX1, pG1,
                             pWt1 + 2 * F * F, pWt2 + 2 * F * F,
                             pWt1 + 3 * F * F, pWt2 + 3 * F * F,
                             b2, pA, pSh, N_NODES);
    k_spmm2<<<SPMM2_BLOCKS, 256>>>(out);

    // ---- head ----
    k_out<<<1, 128>>>(e2pw, e2pb, out);
}

// round 11
// speedup vs baseline: 1.0571x; 1.0571x over previous
#include <cuda_runtime.h>
#include <cuda_bf16.h>
#include <cuda_fp16.h>
#include <math.h>
#include <stdint.h>

#define N_NODES 100000
#define E_EDGES 3200000
#define F 256
#define NOUT 128

#define SCAN_BLK 256
#define SCAN_NBLK ((N_NODES + SCAN_BLK - 1) / SCAN_BLK)   // 391

// ---------------- scratch (device globals; no allocation allowed) ----------
__device__ __half g_Sh[N_NODES * F]; // support = x @ W_nb (fp16 for cheap gather)
__device__ float g_A [N_NODES * F];  // x@W_self + b (GEMM output, SpMM base)
__device__ float g_X1[N_NODES * F];  // x after layer-1 relu
__device__ float g_g1[N_NODES];
__device__ float g_g2[N_NODES];
__device__ float g_z [N_NODES];
__device__ float g_r [N_NODES];
__device__ float g_part[512 * 4];
__device__ float g_stat[4];
__device__ float g_colsum[F];

// transposed + split weights: [wid][n*256+k], wid: 0=self1 1=nb1 2=self2 3=nb2
__device__ __nv_bfloat16 g_Wt1[4 * F * F];
__device__ __nv_bfloat16 g_Wt2[4 * F * F];

// CSR scratch
__device__ int   g_cnt[N_NODES];
__device__ int   g_rowptr[N_NODES + 1];
__device__ int   g_bsum[SCAN_NBLK];
__device__ int   g_boff[SCAN_NBLK];
__device__ int   g_csr_col[E_EDGES];
__device__ float g_csr_val[E_EDGES];

#define NEG_BIG (-3.0e38f)
#define SMEM_SWIZZLE_128B(o) ((o) ^ (((o) >> 3) & 0x70))

__device__ __forceinline__ uint32_t smem_u32(const void* p) {
    uint32_t a;
    asm("{ .reg .u64 t; cvta.to.shared.u64 t, %1; cvt.u32.u64 %0, t; }"
        : "=r"(a) : "l"(p));
    return a;
}

__device__ __forceinline__ void ldmatrix_x4(uint32_t* r, uint32_t addr) {
    asm volatile("ldmatrix.sync.aligned.m8n8.x4.shared.b16 {%0,%1,%2,%3}, [%4];"
        : "=r"(r[0]), "=r"(r[1]), "=r"(r[2]), "=r"(r[3]) : "r"(addr));
}

__device__ __forceinline__ void mma_bf16(float* d, const uint32_t* a, const uint32_t* b) {
    asm volatile(
        "mma.sync.aligned.m16n8k16.row.col.f32.bf16.bf16.f32 "
        "{%0,%1,%2,%3}, {%4,%5,%6,%7}, {%8,%9}, {%0,%1,%2,%3};"
        : "+f"(d[0]), "+f"(d[1]), "+f"(d[2]), "+f"(d[3])
        : "r"(a[0]), "r"(a[1]), "r"(a[2]), "r"(a[3]), "r"(b[0]), "r"(b[1]));
}

// ---------------- init: zero cnt + colsum in one kernel ----------------
__global__ void k_zero_init() {
    int i = blockIdx.x * blockDim.x + threadIdx.x;
    if (i < N_NODES) g_cnt[i] = 0;
    if (i < F) g_colsum[i] = 0.0f;
}

// ---------------- CSR build ------------------------------------------------
__global__ void k_hist(const int* __restrict__ er) {
    int i = blockIdx.x * blockDim.x + threadIdx.x;
    if (i < E_EDGES) atomicAdd(&g_cnt[er[i]], 1);
}

__device__ __forceinline__ int warp_scan_incl(int v, int lane) {
    #pragma unroll
    for (int off = 1; off < 32; off <<= 1) {
        int t = __shfl_up_sync(0xffffffffu, v, off);
        if (lane >= off) v += t;
    }
    return v;
}

__global__ void k_scan1() {
    __shared__ int wsum[8];
    int t = threadIdx.x;
    int lane = t & 31, wid = t >> 5;
    int i = blockIdx.x * SCAN_BLK + t;
    int v = (i < N_NODES) ? g_cnt[i] : 0;
    int incl = warp_scan_incl(v, lane);
    if (lane == 31) wsum[wid] = incl;
    __syncthreads();
    if (wid == 0) {
        int s = (lane < 8) ? wsum[lane] : 0;
        s = warp_scan_incl(s, lane);
        if (lane < 8) wsum[lane] = s;
    }
    __syncthreads();
    int off = wid ? wsum[wid - 1] : 0;
    incl += off;
    if (i < N_NODES) g_rowptr[i] = incl - v;
    if (t == SCAN_BLK - 1) g_bsum[blockIdx.x] = incl;
}

__global__ void k_scan2() {
    __shared__ int wsum[16];
    int t = threadIdx.x;
    int lane = t & 31, wid = t >> 5;
    int v = (t < SCAN_NBLK) ? g_bsum[t] : 0;
    int incl = warp_scan_incl(v, lane);
    if (lane == 31) wsum[wid] = incl;
    __syncthreads();
    if (wid == 0) {
        int s = (lane < 16) ? wsum[lane] : 0;
        s = warp_scan_incl(s, lane);
        if (lane < 16) wsum[lane] = s;
    }
    __syncthreads();
    int off = wid ? wsum[wid - 1] : 0;
    incl += off;
    if (t < SCAN_NBLK) g_boff[t] = incl - v;
}

__global__ void k_scan3() {
    int i = blockIdx.x * blockDim.x + threadIdx.x;
    if (i < N_NODES) {
        int val = g_rowptr[i] + g_boff[i >> 8];
        g_rowptr[i] = val;
        g_cnt[i] = val;
    }
    if (i == 0) g_rowptr[N_NODES] = E_EDGES;
}

__global__ void k_scatter(const int* __restrict__ er, const int* __restrict__ ec,
                          const float* __restrict__ ev) {
    int i = blockIdx.x * blockDim.x + threadIdx.x;
    if (i < E_EDGES) {
        int row = er[i];
        int pos = atomicAdd(&g_cnt[row], 1);
        g_csr_col[pos] = ec[i];
        g_csr_val[pos] = ev[i];
    }
}

// ---------------- weight transpose + bf16 split (all 4 in one) -------------
__global__ void k_wsplit_all(const float* __restrict__ W0, const float* __restrict__ W1,
                             const float* __restrict__ W2, const float* __restrict__ W3)
{
    int i = blockIdx.x * blockDim.x + threadIdx.x;
    if (i >= F * F) return;
    int w = blockIdx.y;
    const float* W = (w == 0) ? W0 : (w == 1) ? W1 : (w == 2) ? W2 : W3;
    int n = i >> 8, k = i & 255;
    float x = W[k * F + n];
    __nv_bfloat16 h = __float2bfloat16(x);
    g_Wt1[w * F * F + i] = h;
    g_Wt2[w * F * F + i] = __float2bfloat16(x - __bfloat162float(h));
}

// ---------------- fused-split mma.sync dual GEMM ---------------------------
__global__ __launch_bounds__(256, 2) void k_gemm_fused(
    const float* __restrict__ Asrc, const float* __restrict__ rvec,
    const __nv_bfloat16* __restrict__ Ws1, const __nv_bfloat16* __restrict__ Ws2,
    const __nv_bfloat16* __restrict__ Wn1, const __nv_bfloat16* __restrict__ Wn2,
    const float* __restrict__ bias,
    float* __restrict__ Cs, __half* __restrict__ Sn, int M)
{
    extern __shared__ __align__(16) char smem[];

    const int tid  = threadIdx.x;
    const int wid  = tid >> 5;
    const int lane = tid & 31;
    const int rowBlock = blockIdx.x * 128;
    const int nBlock   = blockIdx.y * 64;
    const int grp = wid >> 2;            // 0 = self, 1 = nb
    const int wm  = (wid & 3) * 32;

    const uint32_t sA1u = smem_u32(smem);
    const uint32_t sA2u = sA1u + 16384;
    const uint32_t B1u  = sA1u + 32768 + (grp ? 8192 : 0);
    const uint32_t B2u  = sA1u + 49152 + (grp ? 8192 : 0);

    float acc[2][8][4];
    #pragma unroll
    for (int mi = 0; mi < 2; mi++)
        #pragma unroll
        for (int ni = 0; ni < 8; ni++)
            #pragma unroll
            for (int q = 0; q < 4; q++) acc[mi][ni][q] = 0.0f;

    const int aRow = (lane & 15);
    const int aKc  = (lane >> 4) << 3;
    const int bN   = ((lane >> 4) & 1) * 8 + (lane & 7);
    const int bKc  = ((lane >> 3) & 1) * 8;

    #pragma unroll 1
    for (int k0 = 0; k0 < F; k0 += 64) {
        #pragma unroll
        for (int it = 0; it < 8; it++) {
            int idx = tid + it * 256;
            int r   = idx >> 4;
            int c4  = idx & 15;
            int grow = rowBlock + r;
            float4 v = make_float4(0.f, 0.f, 0.f, 0.f);
            if (grow < M) {
                v = *reinterpret_cast<const float4*>(Asrc + (size_t)grow * F + k0 + c4 * 4);
                if (rvec) {
                    float rr = rvec[grow];
                    v.x *= rr; v.y *= rr; v.z *= rr; v.w *= rr;
                }
            }
            __nv_bfloat162 h01 = __floats2bfloat162_rn(v.x, v.y);
            __nv_bfloat162 h23 = __floats2bfloat162_rn(v.z, v.w);
            float2 f01 = __bfloat1622float2(h01);
            float2 f23 = __bfloat1622float2(h23);
            __nv_bfloat162 l01 = __floats2bfloat162_rn(v.x - f01.x, v.y - f01.y);
            __nv_bfloat162 l23 = __floats2bfloat162_rn(v.z - f23.x, v.w - f23.y);
            uint32_t off = SMEM_SWIZZLE_128B((uint32_t)(r * 128 + c4 * 8));
            uint2 hi, lo;
            hi.x = *reinterpret_cast<uint32_t*>(&h01);
            hi.y = *reinterpret_cast<uint32_t*>(&h23);
            lo.x = *reinterpret_cast<uint32_t*>(&l01);
            lo.y = *reinterpret_cast<uint32_t*>(&l23);
            *reinterpret_cast<uint2*>(smem + off)         = hi;
            *reinterpret_cast<uint2*>(smem + 16384 + off) = lo;
        }
        #pragma unroll
        for (int t = 0; t < 4; t++) {
            const __nv_bfloat16* Wp = (t == 0) ? Ws1 : (t == 1) ? Wn1 : (t == 2) ? Ws2 : Wn2;
            char* dst = smem + 32768 + t * 8192;
            #pragma unroll
            for (int it = 0; it < 2; it++) {
                int idx = tid + it * 256;
                int r = idx >> 3, c = idx & 7;
                uint32_t off = SMEM_SWIZZLE_128B((uint32_t)(r * 128 + c * 16));
                *reinterpret_cast<uint4*>(dst + off) =
                    *reinterpret_cast<const uint4*>(Wp + (size_t)(nBlock + r) * F + k0 + c * 8);
            }
        }
        __syncthreads();

        #pragma unroll 1
        for (int combo = 0; combo < 3; combo++) {
            const uint32_t Au = (combo == 1) ? sA2u : sA1u;
            const uint32_t Bu = (combo == 2) ? B2u  : B1u;
            #pragma unroll
            for (int kk = 0; kk < 64; kk += 16) {
                uint32_t a[2][4];
                #pragma unroll
                for (int mi = 0; mi < 2; mi++) {
                    int row = wm + mi * 16 + aRow;
                    ldmatrix_x4(a[mi], Au +
                        SMEM_SWIZZLE_128B((uint32_t)(row * 128 + (kk + aKc) * 2)));
                }
                uint32_t b[8][2];
                #pragma unroll
                for (int np = 0; np < 4; np++) {
                    uint32_t r4[4];
                    int n = np * 16 + bN;
                    ldmatrix_x4(r4, Bu +
                        SMEM_SWIZZLE_128B((uint32_t)(n * 128 + (kk + bKc) * 2)));
                    b[np * 2][0]     = r4[0];
                    b[np * 2][1]     = r4[1];
                    b[np * 2 + 1][0] = r4[2];
                    b[np * 2 + 1][1] = r4[3];
                }
                #pragma unroll
                for (int mi = 0; mi < 2; mi++)
                    #pragma unroll
                    for (int ni = 0; ni < 8; ni++)
                        mma_bf16(acc[mi][ni], a[mi], b[ni]);
            }
        }
        __syncthreads();
    }

    const int rq = lane >> 2;
    const int cq = (lane & 3) * 2;
    if (grp == 0) {
        #pragma unroll
        for (int mi = 0; mi < 2; mi++) {
            #pragma unroll
            for (int ni = 0; ni < 8; ni++) {
                int n = nBlock + ni * 8 + cq;
                float b0 = bias[n], b1 = bias[n + 1];
                int m0 = rowBlock + wm + mi * 16 + rq;
                if (m0 < M)
                    *reinterpret_cast<float2*>(Cs + (size_t)m0 * F + n) =
                        make_float2(acc[mi][ni][0] + b0, acc[mi][ni][1] + b1);
                int m1 = m0 + 8;
                if (m1 < M)
                    *reinterpret_cast<float2*>(Cs + (size_t)m1 * F + n) =
                        make_float2(acc[mi][ni][2] + b0, acc[mi][ni][3] + b1);
            }
        }
    } else {
        #pragma unroll
        for (int mi = 0; mi < 2; mi++) {
            #pragma unroll
            for (int ni = 0; ni < 8; ni++) {
                int n = nBlock + ni * 8 + cq;
                int m0 = rowBlock + wm + mi * 16 + rq;
                if (m0 < M)
                    *reinterpret_cast<__half2*>(Sn + (size_t)m0 * F + n) =
                        __floats2half2_rn(acc[mi][ni][0], acc[mi][ni][1]);
                int m1 = m0 + 8;
                if (m1 < M)
                    *reinterpret_cast<__half2*>(Sn + (size_t)m1 * F + n) =
                        __floats2half2_rn(acc[mi][ni][2], acc[mi][ni][3]);
            }
        }
    }
}

// ---------------- shared SpMM edge-gather core -----------------------------
__device__ __forceinline__ void spmm_row(int s, int e, int lane, float* acc)
{
    const uint4* Sv = reinterpret_cast<const uint4*>(g_Sh);
    #pragma unroll
    for (int j = 0; j < 8; j++) acc[j] = 0.f;

    int i = s;
    for (; i + 3 < e; i += 4) {
        int c0 = g_csr_col[i],     c1 = g_csr_col[i + 1];
        int c2 = g_csr_col[i + 2], c3 = g_csr_col[i + 3];
        float v0 = g_csr_val[i],     v1 = g_csr_val[i + 1];
        float v2 = g_csr_val[i + 2], v3 = g_csr_val[i + 3];
        uint4 q0 = __ldg(Sv + (size_t)c0 * 32 + lane);
        uint4 q1 = __ldg(Sv + (size_t)c1 * 32 + lane);
        uint4 q2 = __ldg(Sv + (size_t)c2 * 32 + lane);
        uint4 q3 = __ldg(Sv + (size_t)c3 * 32 + lane);
        const __half2* h0 = reinterpret_cast<const __half2*>(&q0);
        const __half2* h1 = reinterpret_cast<const __half2*>(&q1);
        const __half2* h2 = reinterpret_cast<const __half2*>(&q2);
        const __half2* h3 = reinterpret_cast<const __half2*>(&q3);
        #pragma unroll
        for (int j = 0; j < 4; j++) {
            float2 f0 = __half22float2(h0[j]);
            float2 f1 = __half22float2(h1[j]);
            float2 f2 = __half22float2(h2[j]);
            float2 f3 = __half22float2(h3[j]);
            acc[2 * j]     += v0 * f0.x + v1 * f1.x + v2 * f2.x + v3 * f3.x;
            acc[2 * j + 1] += v0 * f0.y + v1 * f1.y + v2 * f2.y + v3 * f3.y;
        }
    }
    for (; i < e; i++) {
        int   c0 = g_csr_col[i];
        float v0 = g_csr_val[i];
        uint4 q0 = __ldg(Sv + (size_t)c0 * 32 + lane);
        const __half2* h0 = reinterpret_cast<const __half2*>(&q0);
        #pragma unroll
        for (int j = 0; j < 4; j++) {
            float2 f0 = __half22float2(h0[j]);
            acc[2 * j]     += v0 * f0.x;
            acc[2 * j + 1] += v0 * f0.y;
        }
    }
}

// ---------------- SpMM-1 fused: relu -> X1 + gate dots ---------------------
__global__ __launch_bounds__(256) void k_spmm1(
    const float* __restrict__ w1, const float* __restrict__ b1g,
    const float* __restrict__ w2, const float* __restrict__ b2g)
{
    int warp = (blockIdx.x * blockDim.x + threadIdx.x) >> 5;
    int lane = threadIdx.x & 31;
    if (warp >= N_NODES) return;

    float acc[8];
    spmm_row(g_rowptr[warp], g_rowptr[warp + 1], lane, acc);

    const float* Ap = g_A + (size_t)warp * F + lane * 8;
    float4 b0 = *reinterpret_cast<const float4*>(Ap);
    float4 b1 = *reinterpret_cast<const float4*>(Ap + 4);
    float x[8];
    x[0] = fmaxf(b0.x + acc[0], 0.f); x[1] = fmaxf(b0.y + acc[1], 0.f);
    x[2] = fmaxf(b0.z + acc[2], 0.f); x[3] = fmaxf(b0.w + acc[3], 0.f);
    x[4] = fmaxf(b1.x + acc[4], 0.f); x[5] = fmaxf(b1.y + acc[5], 0.f);
    x[6] = fmaxf(b1.z + acc[6], 0.f); x[7] = fmaxf(b1.w + acc[7], 0.f);

    float* Xp = g_X1 + (size_t)warp * F + lane * 8;
    *reinterpret_cast<float4*>(Xp)     = make_float4(x[0], x[1], x[2], x[3]);
    *reinterpret_cast<float4*>(Xp + 4) = make_float4(x[4], x[5], x[6], x[7]);

    float4 u0 = __ldg(reinterpret_cast<const float4*>(w1 + lane * 8));
    float4 u1 = __ldg(reinterpret_cast<const float4*>(w1 + lane * 8 + 4));
    float4 t0 = __ldg(reinterpret_cast<const float4*>(w2 + lane * 8));
    float4 t1 = __ldg(reinterpret_cast<const float4*>(w2 + lane * 8 + 4));
    float d1 = x[0]*u0.x + x[1]*u0.y + x[2]*u0.z + x[3]*u0.w
             + x[4]*u1.x + x[5]*u1.y + x[6]*u1.z + x[7]*u1.w;
    float d2 = x[0]*t0.x + x[1]*t0.y + x[2]*t0.z + x[3]*t0.w
             + x[4]*t1.x + x[5]*t1.y + x[6]*t1.z + x[7]*t1.w;
    #pragma unroll
    for (int off = 16; off; off >>= 1) {
        d1 += __shfl_xor_sync(0xffffffffu, d1, off);
        d2 += __shfl_xor_sync(0xffffffffu, d2, off);
    }
    if (lane == 0) {
        g_g1[warp] = d1 + b1g[0];
        g_g2[warp] = d2 + b2g[0];
    }
}

// ---------------- SpMM-2 fused: relu, mix, write out, colsum ---------------
#define SPMM2_BLOCKS 1600
__global__ __launch_bounds__(256) void k_spmm2(float* __restrict__ out)
{
    __shared__ float cs[F];
    int tid  = threadIdx.x;
    int lane = tid & 31;
    if (tid < F) cs[tid] = 0.f;
    __syncthreads();

    float local[8];
    #pragma unroll
    for (int j = 0; j < 8; j++) local[j] = 0.f;

    int warpG  = (blockIdx.x * blockDim.x + tid) >> 5;
    int nWarps = SPMM2_BLOCKS * (256 / 32);

    for (int row = warpG; row < N_NODES; row += nWarps) {
        float acc[8];
        spmm_row(g_rowptr[row], g_rowptr[row + 1], lane, acc);

        const float* Ap = g_A + (size_t)row * F + lane * 8;
        float4 b0 = *reinterpret_cast<const float4*>(Ap);
        float4 b1 = *reinterpret_cast<const float4*>(Ap + 4);
        float x2[8];
        x2[0] = fmaxf(b0.x + acc[0], 0.f); x2[1] = fmaxf(b0.y + acc[1], 0.f);
        x2[2] = fmaxf(b0.z + acc[2], 0.f); x2[3] = fmaxf(b0.w + acc[3], 0.f);
        x2[4] = fmaxf(b1.x + acc[4], 0.f); x2[5] = fmaxf(b1.y + acc[5], 0.f);
        x2[6] = fmaxf(b1.z + acc[6], 0.f); x2[7] = fmaxf(b1.w + acc[7], 0.f);

        float z  = g_z[row];
        float iz = 1.f - z;
        const float* Xp = g_X1 + (size_t)row * F + lane * 8;
        float4 x10 = *reinterpret_cast<const float4*>(Xp);
        float4 x11 = *reinterpret_cast<const float4*>(Xp + 4);
        float xe[8];
        xe[0] = iz * x10.x + z * x2[0]; xe[1] = iz * x10.y + z * x2[1];
        xe[2] = iz * x10.z + z * x2[2]; xe[3] = iz * x10.w + z * x2[3];
        xe[4] = iz * x11.x + z * x2[4]; xe[5] = iz * x11.y + z * x2[5];
        xe[6] = iz * x11.z + z * x2[6]; xe[7] = iz * x11.w + z * x2[7];

        float* Op = out + (size_t)row * F + lane * 8;
        *reinterpret_cast<float4*>(Op)     = make_float4(xe[0], xe[1], xe[2], xe[3]);
        *reinterpret_cast<float4*>(Op + 4) = make_float4(xe[4], xe[5], xe[6], xe[7]);

        #pragma unroll
        for (int j = 0; j < 8; j++) local[j] += xe[j];
    }

    #pragma unroll
    for (int j = 0; j < 8; j++)
        atomicAdd(&cs[lane * 8 + j], local[j]);
    __syncthreads();
    if (tid < F) atomicAdd(&g_colsum[tid], cs[tid]);
}

// ---------------- softmax over nodes: online (max, sumexp) -----------------
__device__ __forceinline__ void merge_ms(float& m, float& s, float mb, float sb) {
    float M = fmaxf(m, mb);
    s = s * __expf(m - M) + sb * __expf(mb - M);
    m = M;
}

__global__ void k_softmax_part()
{
    float m1 = NEG_BIG, s1 = 0.f, m2 = NEG_BIG, s2 = 0.f;
    for (int i = blockIdx.x * blockDim.x + threadIdx.x; i < N_NODES;
         i += gridDim.x * blockDim.x) {
        float v1 = g_g1[i];
        merge_ms(m1, s1, v1, 1.0f);
        float v2 = g_g2[i];
        merge_ms(m2, s2, v2, 1.0f);
    }
    __shared__ float sm1[256], ss1[256], sm2[256], ss2[256];
    int t = threadIdx.x;
    sm1[t] = m1; ss1[t] = s1; sm2[t] = m2; ss2[t] = s2;
    __syncthreads();
    for (int off = 128; off; off >>= 1) {
        if (t < off) {
            float mm = sm1[t], ss = ss1[t];
            merge_ms(mm, ss, sm1[t + off], ss1[t + off]);
            sm1[t] = mm; ss1[t] = ss;
            mm = sm2[t]; ss = ss2[t];
            merge_ms(mm, ss, sm2[t + off], ss2[t + off]);
            sm2[t] = mm; ss2[t] = ss;
        }
        __syncthreads();
    }
    if (t == 0) {
        g_part[blockIdx.x * 4 + 0] = sm1[0];
        g_part[blockIdx.x * 4 + 1] = ss1[0];
        g_part[blockIdx.x * 4 + 2] = sm2[0];
        g_part[blockIdx.x * 4 + 3] = ss2[0];
    }
}

__global__ void k_softmax_final(int nparts)
{
    __shared__ float sm1[128], ss1[128], sm2[128], ss2[128];
    int t = threadIdx.x;
    float m1 = NEG_BIG, s1 = 0.f, m2 = NEG_BIG, s2 = 0.f;
    if (t < nparts) {
        m1 = g_part[t * 4 + 0]; s1 = g_part[t * 4 + 1];
        m2 = g_part[t * 4 + 2]; s2 = g_part[t * 4 + 3];
    }
    sm1[t] = m1; ss1[t] = s1; sm2[t] = m2; ss2[t] = s2;
    __syncthreads();
    for (int off = 64; off; off >>= 1) {
        if (t < off) {
            float mm = sm1[t], ss = ss1[t];
            merge_ms(mm, ss, sm1[t + off], ss1[t + off]);
            sm1[t] = mm; ss1[t] = ss;
            mm = sm2[t]; ss = ss2[t];
            merge_ms(mm, ss, sm2[t + off], ss2[t + off]);
            sm2[t] = mm; ss2[t] = ss;
        }
        __syncthreads();
    }
    if (t == 0) {
        g_stat[0] = sm1[0]; g_stat[1] = ss1[0];
        g_stat[2] = sm2[0]; g_stat[3] = ss2[0];
    }
}

__global__ void k_rz()
{
    int i = blockIdx.x * blockDim.x + threadIdx.x;
    if (i < N_NODES) {
        g_r[i] = __expf(g_g1[i] - g_stat[0]) / g_stat[1];
        g_z[i] = __expf(g_g2[i] - g_stat[2]) / g_stat[3];
    }
}

// ---------------- output head ---------------------------------------------
__global__ void k_out(const float* __restrict__ e2pw, const float* __restrict__ e2pb,
                      float* __restrict__ out)
{
    __shared__ float mean[F];
    for (int i = threadIdx.x; i < F; i += blockDim.x)
        mean[i] = g_colsum[i] * (1.0f / N_NODES);
    __syncthreads();
    int j = threadIdx.x;
    if (j < NOUT) {
        float acc = e2pb[j];
        #pragma unroll 8
        for (int k = 0; k < F; k++)
            acc += mean[k] * e2pw[(size_t)k * NOUT + j];
        out[(size_t)N_NODES * F + j] = acc;
    }
}

// ---------------- launch ----------------
extern "C" void kernel_launch(void* const* d_in, const int* in_sizes, int n_in,
                              void* d_out, int out_size)
{
    const float* inputs  = (const float*)d_in[0];
    const int*   er      = (const int*)  d_in[1];
    const int*   ec      = (const int*)  d_in[2];
    const float* ev      = (const float*)d_in[3];
    const float* W_self1 = (const float*)d_in[4];
    const float* W_nb1   = (const float*)d_in[5];
    const float* b1      = (const float*)d_in[6];
    const float* W_self2 = (const float*)d_in[7];
    const float* W_nb2   = (const float*)d_in[8];
    const float* b2      = (const float*)d_in[9];
    const float* g1w     = (const float*)d_in[10];
    const float* g1b     = (const float*)d_in[11];
    const float* g2w     = (const float*)d_in[12];
    const float* g2b     = (const float*)d_in[13];
    const float* e2pw    = (const float*)d_in[14];
    const float* e2pb    = (const float*)d_in[15];
    float* out = (float*)d_out;

    float *pA, *pX1, *pR;
    __half* pSh;
    cudaGetSymbolAddress((void**)&pA,  g_A);
    cudaGetSymbolAddress((void**)&pX1, g_X1);
    cudaGetSymbolAddress((void**)&pR,  g_r);
    cudaGetSymbolAddress((void**)&pSh, g_Sh);
    __nv_bfloat16 *pWt1, *pWt2;
    cudaGetSymbolAddress((void**)&pWt1, g_Wt1);
    cudaGetSymbolAddress((void**)&pWt2, g_Wt2);

    const int SMEM_GEMM = 65536;
    cudaFuncSetAttribute(k_gemm_fused, cudaFuncAttributeMaxDynamicSharedMemorySize, SMEM_GEMM);

    const int EB = (E_EDGES + 255) / 256;
    const int NB = (N_NODES + 255) / 256;
    dim3 gmm((N_NODES + 127) / 128, 4);
    dim3 gws((F * F + 255) / 256, 4);

    // ---- CSR build + init ----
    k_zero_init<<<NB, 256>>>();
    k_hist<<<EB, 256>>>(er);
    k_scan1<<<SCAN_NBLK, SCAN_BLK>>>();
    k_scan2<<<1, 512>>>();
    k_scan3<<<NB, 256>>>();
    k_scatter<<<EB, 256>>>(er, ec, ev);

    // ---- weight prep (merged: one launch for all 4 weights) ----
    k_wsplit_all<<<gws, 256>>>(W_self1, W_nb1, W_self2, W_nb2);

    // ---- layer 1 ----
    k_gemm_fused<<<gmm, 256, SMEM_GEMM>>>(inputs, nullptr,
                             pWt1 + 0 * F * F, pWt2 + 0 * F * F,
                             pWt1 + 1 * F * F, pWt2 + 1 * F * F,
                             b1, pA, pSh, N_NODES);
    k_spmm1<<<(N_NODES * 32 + 255) / 256, 256>>>(g1w, g1b, g2w, g2b);

    // ---- softmax gates over nodes ----
    k_softmax_part<<<120, 256>>>();
    k_softmax_final<<<1, 128>>>(120);
    k_rz<<<NB, 256>>>();

    // ---- layer 2 (rows of X1 scaled by r) ----
    k_gemm_fused<<<gmm, 256, SMEM_GEMM>>>(pX1, pR,
                             pWt1 + 2 * F * F, pWt2 + 2 * F * F,
                             pWt1 + 3 * F * F, pWt2 + 3 * F * F,
                             b2, pA, pSh, N_NODES);
    k_spmm2<<<SPMM2_BLOCKS, 256>>>(out);

    // ---- head ----
    k_out<<<1, 128>>>(e2pw, e2pb, out);
}

// round 12
// speedup vs baseline: 1.5289x; 1.4464x over previous
#include <cuda_runtime.h>
#include <cuda_bf16.h>
#include <cuda_fp16.h>
#include <math.h>
#include <stdint.h>

#define N_NODES 100000
#define E_EDGES 3200000
#define F 256
#define NOUT 128

#define SCAN_BLK 256
#define SCAN_NBLK ((N_NODES + SCAN_BLK - 1) / SCAN_BLK)   // 391

// ---------------- scratch (device globals; no allocation allowed) ----------
__device__ __half g_Sh[N_NODES * F]; // support = x @ W_nb (fp16 for cheap gather)
__device__ float g_A [N_NODES * F];  // x@W_self + b (GEMM output, SpMM base)
__device__ float g_X1[N_NODES * F];  // x after layer-1 relu
__device__ float g_g1[N_NODES];
__device__ float g_g2[N_NODES];
__device__ float g_z [N_NODES];
__device__ float g_r [N_NODES];
__device__ float g_part[512 * 4];
__device__ float g_stat[4];
__device__ float g_colsum[F];

// transposed + split weights: [wid][n*256+k], wid: 0=self1 1=nb1 2=self2 3=nb2
__device__ __nv_bfloat16 g_Wt1[4 * F * F];
__device__ __nv_bfloat16 g_Wt2[4 * F * F];

// CSR scratch
__device__ int   g_cnt[N_NODES];
__device__ int   g_rowptr[N_NODES + 1];
__device__ int   g_bsum[SCAN_NBLK];
__device__ int   g_boff[SCAN_NBLK];
__device__ int   g_csr_col[E_EDGES];
__device__ float g_csr_val[E_EDGES];

#define NEG_BIG (-3.0e38f)
#define SMEM_SWIZZLE_128B(o) ((o) ^ (((o) >> 3) & 0x70))

__device__ __forceinline__ uint32_t smem_u32(const void* p) {
    uint32_t a;
    asm("{ .reg .u64 t; cvta.to.shared.u64 t, %1; cvt.u32.u64 %0, t; }"
        : "=r"(a) : "l"(p));
    return a;
}

__device__ __forceinline__ void ldmatrix_x4(uint32_t* r, uint32_t addr) {
    asm volatile("ldmatrix.sync.aligned.m8n8.x4.shared.b16 {%0,%1,%2,%3}, [%4];"
        : "=r"(r[0]), "=r"(r[1]), "=r"(r[2]), "=r"(r[3]) : "r"(addr));
}

__device__ __forceinline__ void mma_bf16(float* d, const uint32_t* a, const uint32_t* b) {
    asm volatile(
        "mma.sync.aligned.m16n8k16.row.col.f32.bf16.bf16.f32 "
        "{%0,%1,%2,%3}, {%4,%5,%6,%7}, {%8,%9}, {%0,%1,%2,%3};"
        : "+f"(d[0]), "+f"(d[1]), "+f"(d[2]), "+f"(d[3])
        : "r"(a[0]), "r"(a[1]), "r"(a[2]), "r"(a[3]), "r"(b[0]), "r"(b[1]));
}

// ---------------- init: zero cnt + colsum in one kernel ----------------
__global__ void k_zero_init() {
    int i = blockIdx.x * blockDim.x + threadIdx.x;
    if (i < N_NODES) g_cnt[i] = 0;
    if (i < F) g_colsum[i] = 0.0f;
}

// ---------------- CSR build ------------------------------------------------
__global__ void k_hist(const int* __restrict__ er) {
    int i = blockIdx.x * blockDim.x + threadIdx.x;
    if (i < E_EDGES) atomicAdd(&g_cnt[er[i]], 1);
}

__device__ __forceinline__ int warp_scan_incl(int v, int lane) {
    #pragma unroll
    for (int off = 1; off < 32; off <<= 1) {
        int t = __shfl_up_sync(0xffffffffu, v, off);
        if (lane >= off) v += t;
    }
    return v;
}

__global__ void k_scan1() {
    __shared__ int wsum[8];
    int t = threadIdx.x;
    int lane = t & 31, wid = t >> 5;
    int i = blockIdx.x * SCAN_BLK + t;
    int v = (i < N_NODES) ? g_cnt[i] : 0;
    int incl = warp_scan_incl(v, lane);
    if (lane == 31) wsum[wid] = incl;
    __syncthreads();
    if (wid == 0) {
        int s = (lane < 8) ? wsum[lane] : 0;
        s = warp_scan_incl(s, lane);
        if (lane < 8) wsum[lane] = s;
    }
    __syncthreads();
    int off = wid ? wsum[wid - 1] : 0;
    incl += off;
    if (i < N_NODES) g_rowptr[i] = incl - v;
    if (t == SCAN_BLK - 1) g_bsum[blockIdx.x] = incl;
}

__global__ void k_scan2() {
    __shared__ int wsum[16];
    int t = threadIdx.x;
    int lane = t & 31, wid = t >> 5;
    int v = (t < SCAN_NBLK) ? g_bsum[t] : 0;
    int incl = warp_scan_incl(v, lane);
    if (lane == 31) wsum[wid] = incl;
    __syncthreads();
    if (wid == 0) {
        int s = (lane < 16) ? wsum[lane] : 0;
        s = warp_scan_incl(s, lane);
        if (lane < 16) wsum[lane] = s;
    }
    __syncthreads();
    int off = wid ? wsum[wid - 1] : 0;
    incl += off;
    if (t < SCAN_NBLK) g_boff[t] = incl - v;
}

__global__ void k_scan3() {
    int i = blockIdx.x * blockDim.x + threadIdx.x;
    if (i < N_NODES) {
        int val = g_rowptr[i] + g_boff[i >> 8];
        g_rowptr[i] = val;
        g_cnt[i] = val;
    }
    if (i == 0) g_rowptr[N_NODES] = E_EDGES;
}

__global__ void k_scatter(const int* __restrict__ er, const int* __restrict__ ec,
                          const float* __restrict__ ev) {
    int i = blockIdx.x * blockDim.x + threadIdx.x;
    if (i < E_EDGES) {
        int row = er[i];
        int pos = atomicAdd(&g_cnt[row], 1);
        g_csr_col[pos] = ec[i];
        g_csr_val[pos] = ev[i];
    }
}

// ---------------- weight transpose + bf16 split (all 4 in one) -------------
__global__ void k_wsplit_all(const float* __restrict__ W0, const float* __restrict__ W1,
                             const float* __restrict__ W2, const float* __restrict__ W3)
{
    int i = blockIdx.x * blockDim.x + threadIdx.x;
    if (i >= F * F) return;
    int w = blockIdx.y;
    const float* W = (w == 0) ? W0 : (w == 1) ? W1 : (w == 2) ? W2 : W3;
    int n = i >> 8, k = i & 255;
    float x = W[k * F + n];
    __nv_bfloat16 h = __float2bfloat16(x);
    g_Wt1[w * F * F + i] = h;
    g_Wt2[w * F * F + i] = __float2bfloat16(x - __bfloat162float(h));
}

// ---------------- fused-split mma.sync dual GEMM ---------------------------
// Grid is (4, 782): blockIdx.x = n-slice (fast-varying), blockIdx.y = row block.
// Consecutive bids share the same A row-block -> A read once from DRAM,
// 3 L2 hits, instead of 4 DRAM passes with the x-major (782,4) layout.
__global__ __launch_bounds__(256, 2) void k_gemm_fused(
    const float* __restrict__ Asrc, const float* __restrict__ rvec,
    const __nv_bfloat16* __restrict__ Ws1, const __nv_bfloat16* __restrict__ Ws2,
    const __nv_bfloat16* __restrict__ Wn1, const __nv_bfloat16* __restrict__ Wn2,
    const float* __restrict__ bias,
    float* __restrict__ Cs, __half* __restrict__ Sn, int M)
{
    extern __shared__ __align__(16) char smem[];

    const int tid  = threadIdx.x;
    const int wid  = tid >> 5;
    const int lane = tid & 31;
    const int rowBlock = blockIdx.y * 128;
    const int nBlock   = blockIdx.x * 64;
    const int grp = wid >> 2;            // 0 = self, 1 = nb
    const int wm  = (wid & 3) * 32;

    const uint32_t sA1u = smem_u32(smem);
    const uint32_t sA2u = sA1u + 16384;
    const uint32_t B1u  = sA1u + 32768 + (grp ? 8192 : 0);
    const uint32_t B2u  = sA1u + 49152 + (grp ? 8192 : 0);

    float acc[2][8][4];
    #pragma unroll
    for (int mi = 0; mi < 2; mi++)
        #pragma unroll
        for (int ni = 0; ni < 8; ni++)
            #pragma unroll
            for (int q = 0; q < 4; q++) acc[mi][ni][q] = 0.0f;

    const int aRow = (lane & 15);
    const int aKc  = (lane >> 4) << 3;
    const int bN   = ((lane >> 4) & 1) * 8 + (lane & 7);
    const int bKc  = ((lane >> 3) & 1) * 8;

    #pragma unroll 1
    for (int k0 = 0; k0 < F; k0 += 64) {
        #pragma unroll
        for (int it = 0; it < 8; it++) {
            int idx = tid + it * 256;
            int r   = idx >> 4;
            int c4  = idx & 15;
            int grow = rowBlock + r;
            float4 v = make_float4(0.f, 0.f, 0.f, 0.f);
            if (grow < M) {
                v = *reinterpret_cast<const float4*>(Asrc + (size_t)grow * F + k0 + c4 * 4);
                if (rvec) {
                    float rr = rvec[grow];
                    v.x *= rr; v.y *= rr; v.z *= rr; v.w *= rr;
                }
            }
            __nv_bfloat162 h01 = __floats2bfloat162_rn(v.x, v.y);
            __nv_bfloat162 h23 = __floats2bfloat162_rn(v.z, v.w);
            float2 f01 = __bfloat1622float2(h01);
            float2 f23 = __bfloat1622float2(h23);
            __nv_bfloat162 l01 = __floats2bfloat162_rn(v.x - f01.x, v.y - f01.y);
            __nv_bfloat162 l23 = __floats2bfloat162_rn(v.z - f23.x, v.w - f23.y);
            uint32_t off = SMEM_SWIZZLE_128B((uint32_t)(r * 128 + c4 * 8));
            uint2 hi, lo;
            hi.x = *reinterpret_cast<uint32_t*>(&h01);
            hi.y = *reinterpret_cast<uint32_t*>(&h23);
            lo.x = *reinterpret_cast<uint32_t*>(&l01);
            lo.y = *reinterpret_cast<uint32_t*>(&l23);
            *reinterpret_cast<uint2*>(smem + off)         = hi;
            *reinterpret_cast<uint2*>(smem + 16384 + off) = lo;
        }
        #pragma unroll
        for (int t = 0; t < 4; t++) {
            const __nv_bfloat16* Wp = (t == 0) ? Ws1 : (t == 1) ? Wn1 : (t == 2) ? Ws2 : Wn2;
            char* dst = smem + 32768 + t * 8192;
            #pragma unroll
            for (int it = 0; it < 2; it++) {
                int idx = tid + it * 256;
                int r = idx >> 3, c = idx & 7;
                uint32_t off = SMEM_SWIZZLE_128B((uint32_t)(r * 128 + c * 16));
                *reinterpret_cast<uint4*>(dst + off) =
                    *reinterpret_cast<const uint4*>(Wp + (size_t)(nBlock + r) * F + k0 + c * 8);
            }
        }
        __syncthreads();

        #pragma unroll 1
        for (int combo = 0; combo < 3; combo++) {
            const uint32_t Au = (combo == 1) ? sA2u : sA1u;
            const uint32_t Bu = (combo == 2) ? B2u  : B1u;
            #pragma unroll
            for (int kk = 0; kk < 64; kk += 16) {
                uint32_t a[2][4];
                #pragma unroll
                for (int mi = 0; mi < 2; mi++) {
                    int row = wm + mi * 16 + aRow;
                    ldmatrix_x4(a[mi], Au +
                        SMEM_SWIZZLE_128B((uint32_t)(row * 128 + (kk + aKc) * 2)));
                }
                uint32_t b[8][2];
                #pragma unroll
                for (int np = 0; np < 4; np++) {
                    uint32_t r4[4];
                    int n = np * 16 + bN;
                    ldmatrix_x4(r4, Bu +
                        SMEM_SWIZZLE_128B((uint32_t)(n * 128 + (kk + bKc) * 2)));
                    b[np * 2][0]     = r4[0];
                    b[np * 2][1]     = r4[1];
                    b[np * 2 + 1][0] = r4[2];
                    b[np * 2 + 1][1] = r4[3];
                }
                #pragma unroll
                for (int mi = 0; mi < 2; mi++)
                    #pragma unroll
                    for (int ni = 0; ni < 8; ni++)
                        mma_bf16(acc[mi][ni], a[mi], b[ni]);
            }
        }
        __syncthreads();
    }

    const int rq = lane >> 2;
    const int cq = (lane & 3) * 2;
    if (grp == 0) {
        #pragma unroll
        for (int mi = 0; mi < 2; mi++) {
            #pragma unroll
            for (int ni = 0; ni < 8; ni++) {
                int n = nBlock + ni * 8 + cq;
                float b0 = bias[n], b1 = bias[n + 1];
                int m0 = rowBlock + wm + mi * 16 + rq;
                if (m0 < M)
                    *reinterpret_cast<float2*>(Cs + (size_t)m0 * F + n) =
                        make_float2(acc[mi][ni][0] + b0, acc[mi][ni][1] + b1);
                int m1 = m0 + 8;
                if (m1 < M)
                    *reinterpret_cast<float2*>(Cs + (size_t)m1 * F + n) =
                        make_float2(acc[mi][ni][2] + b0, acc[mi][ni][3] + b1);
            }
        }
    } else {
        #pragma unroll
        for (int mi = 0; mi < 2; mi++) {
            #pragma unroll
            for (int ni = 0; ni < 8; ni++) {
                int n = nBlock + ni * 8 + cq;
                int m0 = rowBlock + wm + mi * 16 + rq;
                if (m0 < M)
                    *reinterpret_cast<__half2*>(Sn + (size_t)m0 * F + n) =
                        __floats2half2_rn(acc[mi][ni][0], acc[mi][ni][1]);
                int m1 = m0 + 8;
                if (m1 < M)
                    *reinterpret_cast<__half2*>(Sn + (size_t)m1 * F + n) =
                        __floats2half2_rn(acc[mi][ni][2], acc[mi][ni][3]);
            }
        }
    }
}

// ---------------- shared SpMM edge-gather core -----------------------------
__device__ __forceinline__ void spmm_row(int s, int e, int lane, float* acc)
{
    const uint4* Sv = reinterpret_cast<const uint4*>(g_Sh);
    #pragma unroll
    for (int j = 0; j < 8; j++) acc[j] = 0.f;

    int i = s;
    for (; i + 3 < e; i += 4) {
        int c0 = g_csr_col[i],     c1 = g_csr_col[i + 1];
        int c2 = g_csr_col[i + 2], c3 = g_csr_col[i + 3];
        float v0 = g_csr_val[i],     v1 = g_csr_val[i + 1];
        float v2 = g_csr_val[i + 2], v3 = g_csr_val[i + 3];
        uint4 q0 = __ldg(Sv + (size_t)c0 * 32 + lane);
        uint4 q1 = __ldg(Sv + (size_t)c1 * 32 + lane);
        uint4 q2 = __ldg(Sv + (size_t)c2 * 32 + lane);
        uint4 q3 = __ldg(Sv + (size_t)c3 * 32 + lane);
        const __half2* h0 = reinterpret_cast<const __half2*>(&q0);
        const __half2* h1 = reinterpret_cast<const __half2*>(&q1);
        const __half2* h2 = reinterpret_cast<const __half2*>(&q2);
        const __half2* h3 = reinterpret_cast<const __half2*>(&q3);
        #pragma unroll
        for (int j = 0; j < 4; j++) {
            float2 f0 = __half22float2(h0[j]);
            float2 f1 = __half22float2(h1[j]);
            float2 f2 = __half22float2(h2[j]);
            float2 f3 = __half22float2(h3[j]);
            acc[2 * j]     += v0 * f0.x + v1 * f1.x + v2 * f2.x + v3 * f3.x;
            acc[2 * j + 1] += v0 * f0.y + v1 * f1.y + v2 * f2.y + v3 * f3.y;
        }
    }
    for (; i < e; i++) {
        int   c0 = g_csr_col[i];
        float v0 = g_csr_val[i];
        uint4 q0 = __ldg(Sv + (size_t)c0 * 32 + lane);
        const __half2* h0 = reinterpret_cast<const __half2*>(&q0);
        #pragma unroll
        for (int j = 0; j < 4; j++) {
            float2 f0 = __half22float2(h0[j]);
            acc[2 * j]     += v0 * f0.x;
            acc[2 * j + 1] += v0 * f0.y;
        }
    }
}

// ---------------- SpMM-1 fused: relu -> X1 + gate dots ---------------------
__global__ __launch_bounds__(256) void k_spmm1(
    const float* __restrict__ w1, const float* __restrict__ b1g,
    const float* __restrict__ w2, const float* __restrict__ b2g)
{
    int warp = (blockIdx.x * blockDim.x + threadIdx.x) >> 5;
    int lane = threadIdx.x & 31;
    if (warp >= N_NODES) return;

    float acc[8];
    spmm_row(g_rowptr[warp], g_rowptr[warp + 1], lane, acc);

    const float* Ap = g_A + (size_t)warp * F + lane * 8;
    float4 b0 = *reinterpret_cast<const float4*>(Ap);
    float4 b1 = *reinterpret_cast<const float4*>(Ap + 4);
    float x[8];
    x[0] = fmaxf(b0.x + acc[0], 0.f); x[1] = fmaxf(b0.y + acc[1], 0.f);
    x[2] = fmaxf(b0.z + acc[2], 0.f); x[3] = fmaxf(b0.w + acc[3], 0.f);
    x[4] = fmaxf(b1.x + acc[4], 0.f); x[5] = fmaxf(b1.y + acc[5], 0.f);
    x[6] = fmaxf(b1.z + acc[6], 0.f); x[7] = fmaxf(b1.w + acc[7], 0.f);

    float* Xp = g_X1 + (size_t)warp * F + lane * 8;
    *reinterpret_cast<float4*>(Xp)     = make_float4(x[0], x[1], x[2], x[3]);
    *reinterpret_cast<float4*>(Xp + 4) = make_float4(x[4], x[5], x[6], x[7]);

    float4 u0 = __ldg(reinterpret_cast<const float4*>(w1 + lane * 8));
    float4 u1 = __ldg(reinterpret_cast<const float4*>(w1 + lane * 8 + 4));
    float4 t0 = __ldg(reinterpret_cast<const float4*>(w2 + lane * 8));
    float4 t1 = __ldg(reinterpret_cast<const float4*>(w2 + lane * 8 + 4));
    float d1 = x[0]*u0.x + x[1]*u0.y + x[2]*u0.z + x[3]*u0.w
             + x[4]*u1.x + x[5]*u1.y + x[6]*u1.z + x[7]*u1.w;
    float d2 = x[0]*t0.x + x[1]*t0.y + x[2]*t0.z + x[3]*t0.w
             + x[4]*t1.x + x[5]*t1.y + x[6]*t1.z + x[7]*t1.w;
    #pragma unroll
    for (int off = 16; off; off >>= 1) {
        d1 += __shfl_xor_sync(0xffffffffu, d1, off);
        d2 += __shfl_xor_sync(0xffffffffu, d2, off);
    }
    if (lane == 0) {
        g_g1[warp] = d1 + b1g[0];
        g_g2[warp] = d2 + b2g[0];
    }
}

// ---------------- SpMM-2 fused: relu, mix, write out, colsum ---------------
#define SPMM2_BLOCKS 1600
__global__ __launch_bounds__(256) void k_spmm2(float* __restrict__ out)
{
    __shared__ float cs[F];
    int tid  = threadIdx.x;
    int lane = tid & 31;
    if (tid < F) cs[tid] = 0.f;
    __syncthreads();

    float local[8];
    #pragma unroll
    for (int j = 0; j < 8; j++) local[j] = 0.f;

    int warpG  = (blockIdx.x * blockDim.x + tid) >> 5;
    int nWarps = SPMM2_BLOCKS * (256 / 32);

    for (int row = warpG; row < N_NODES; row += nWarps) {
        float acc[8];
        spmm_row(g_rowptr[row], g_rowptr[row + 1], lane, acc);

        const float* Ap = g_A + (size_t)row * F + lane * 8;
        float4 b0 = *reinterpret_cast<const float4*>(Ap);
        float4 b1 = *reinterpret_cast<const float4*>(Ap + 4);
        float x2[8];
        x2[0] = fmaxf(b0.x + acc[0], 0.f); x2[1] = fmaxf(b0.y + acc[1], 0.f);
        x2[2] = fmaxf(b0.z + acc[2], 0.f); x2[3] = fmaxf(b0.w + acc[3], 0.f);
        x2[4] = fmaxf(b1.x + acc[4], 0.f); x2[5] = fmaxf(b1.y + acc[5], 0.f);
        x2[6] = fmaxf(b1.z + acc[6], 0.f); x2[7] = fmaxf(b1.w + acc[7], 0.f);

        float z  = g_z[row];
        float iz = 1.f - z;
        const float* Xp = g_X1 + (size_t)row * F + lane * 8;
        float4 x10 = *reinterpret_cast<const float4*>(Xp);
        float4 x11 = *reinterpret_cast<const float4*>(Xp + 4);
        float xe[8];
        xe[0] = iz * x10.x + z * x2[0]; xe[1] = iz * x10.y + z * x2[1];
        xe[2] = iz * x10.z + z * x2[2]; xe[3] = iz * x10.w + z * x2[3];
        xe[4] = iz * x11.x + z * x2[4]; xe[5] = iz * x11.y + z * x2[5];
        xe[6] = iz * x11.z + z * x2[6]; xe[7] = iz * x11.w + z * x2[7];

        float* Op = out + (size_t)row * F + lane * 8;
        *reinterpret_cast<float4*>(Op)     = make_float4(xe[0], xe[1], xe[2], xe[3]);
        *reinterpret_cast<float4*>(Op + 4) = make_float4(xe[4], xe[5], xe[6], xe[7]);

        #pragma unroll
        for (int j = 0; j < 8; j++) local[j] += xe[j];
    }

    #pragma unroll
    for (int j = 0; j < 8; j++)
        atomicAdd(&cs[lane * 8 + j], local[j]);
    __syncthreads();
    if (tid < F) atomicAdd(&g_colsum[tid], cs[tid]);
}

// ---------------- softmax over nodes: online (max, sumexp) -----------------
__device__ __forceinline__ void merge_ms(float& m, float& s, float mb, float sb) {
    float M = fmaxf(m, mb);
    s = s * __expf(m - M) + sb * __expf(mb - M);
    m = M;
}

__global__ void k_softmax_part()
{
    float m1 = NEG_BIG, s1 = 0.f, m2 = NEG_BIG, s2 = 0.f;
    for (int i = blockIdx.x * blockDim.x + threadIdx.x; i < N_NODES;
         i += gridDim.x * blockDim.x) {
        float v1 = g_g1[i];
        merge_ms(m1, s1, v1, 1.0f);
        float v2 = g_g2[i];
        merge_ms(m2, s2, v2, 1.0f);
    }
    __shared__ float sm1[256], ss1[256], sm2[256], ss2[256];
    int t = threadIdx.x;
    sm1[t] = m1; ss1[t] = s1; sm2[t] = m2; ss2[t] = s2;
    __syncthreads();
    for (int off = 128; off; off >>= 1) {
        if (t < off) {
            float mm = sm1[t], ss = ss1[t];
            merge_ms(mm, ss, sm1[t + off], ss1[t + off]);
            sm1[t] = mm; ss1[t] = ss;
            mm = sm2[t]; ss = ss2[t];
            merge_ms(mm, ss, sm2[t + off], ss2[t + off]);
            sm2[t] = mm; ss2[t] = ss;
        }
        __syncthreads();
    }
    if (t == 0) {
        g_part[blockIdx.x * 4 + 0] = sm1[0];
        g_part[blockIdx.x * 4 + 1] = ss1[0];
        g_part[blockIdx.x * 4 + 2] = sm2[0];
        g_part[blockIdx.x * 4 + 3] = ss2[0];
    }
}

__global__ void k_softmax_final(int nparts)
{
    __shared__ float sm1[128], ss1[128], sm2[128], ss2[128];
    int t = threadIdx.x;
    float m1 = NEG_BIG, s1 = 0.f, m2 = NEG_BIG, s2 = 0.f;
    if (t < nparts) {
        m1 = g_part[t * 4 + 0]; s1 = g_part[t * 4 + 1];
        m2 = g_part[t * 4 + 2]; s2 = g_part[t * 4 + 3];
    }
    sm1[t] = m1; ss1[t] = s1; sm2[t] = m2; ss2[t] = s2;
    __syncthreads();
    for (int off = 64; off; off >>= 1) {
        if (t < off) {
            float mm = sm1[t], ss = ss1[t];
            merge_ms(mm, ss, sm1[t + off], ss1[t + off]);
            sm1[t] = mm; ss1[t] = ss;
            mm = sm2[t]; ss = ss2[t];
            merge_ms(mm, ss, sm2[t + off], ss2[t + off]);
            sm2[t] = mm; ss2[t] = ss;
        }
        __syncthreads();
    }
    if (t == 0) {
        g_stat[0] = sm1[0]; g_stat[1] = ss1[0];
        g_stat[2] = sm2[0]; g_stat[3] = ss2[0];
    }
}

__global__ void k_rz()
{
    int i = blockIdx.x * blockDim.x + threadIdx.x;
    if (i < N_NODES) {
        g_r[i] = __expf(g_g1[i] - g_stat[0]) / g_stat[1];
        g_z[i] = __expf(g_g2[i] - g_stat[2]) / g_stat[3];
    }
}

// ---------------- output head ---------------------------------------------
__global__ void k_out(const float* __restrict__ e2pw, const float* __restrict__ e2pb,
                      float* __restrict__ out)
{
    __shared__ float mean[F];
    for (int i = threadIdx.x; i < F; i += blockDim.x)
        mean[i] = g_colsum[i] * (1.0f / N_NODES);
    __syncthreads();
    int j = threadIdx.x;
    if (j < NOUT) {
        float acc = e2pb[j];
        #pragma unroll 8
        for (int k = 0; k < F; k++)
            acc += mean[k] * e2pw[(size_t)k * NOUT + j];
        out[(size_t)N_NODES * F + j] = acc;
    }
}

// ---------------- launch ----------------
extern "C" void kernel_launch(void* const* d_in, const int* in_sizes, int n_in,
                              void* d_out, int out_size)
{
    const float* inputs  = (const float*)d_in[0];
    const int*   er      = (const int*)  d_in[1];
    const int*   ec      = (const int*)  d_in[2];
    const float* ev      = (const float*)d_in[3];
    const float* W_self1 = (const float*)d_in[4];
    const float* W_nb1   = (const float*)d_in[5];
    const float* b1      = (const float*)d_in[6];
    const float* W_self2 = (const float*)d_in[7];
    const float* W_nb2   = (const float*)d_in[8];
    const float* b2      = (const float*)d_in[9];
    const float* g1w     = (const float*)d_in[10];
    const float* g1b     = (const float*)d_in[11];
    const float* g2w     = (const float*)d_in[12];
    const float* g2b     = (const float*)d_in[13];
    const float* e2pw    = (const float*)d_in[14];
    const float* e2pb    = (const float*)d_in[15];
    float* out = (float*)d_out;

    float *pA, *pX1, *pR;
    __half* pSh;
    cudaGetSymbolAddress((void**)&pA,  g_A);
    cudaGetSymbolAddress((void**)&pX1, g_X1);
    cudaGetSymbolAddress((void**)&pR,  g_r);
    cudaGetSymbolAddress((void**)&pSh, g_Sh);
    __nv_bfloat16 *pWt1, *pWt2;
    cudaGetSymbolAddress((void**)&pWt1, g_Wt1);
    cudaGetSymbolAddress((void**)&pWt2, g_Wt2);

    const int SMEM_GEMM = 65536;
    cudaFuncSetAttribute(k_gemm_fused, cudaFuncAttributeMaxDynamicSharedMemorySize, SMEM_GEMM);

    const int EB = (E_EDGES + 255) / 256;
    const int NB = (N_NODES + 255) / 256;
    dim3 gmm(4, (N_NODES + 127) / 128);    // n-slice fast-varying: A tile shared in L2
    dim3 gws((F * F + 255) / 256, 4);

    // ---- CSR build + init ----
    k_zero_init<<<NB, 256>>>();
    k_hist<<<EB, 256>>>(er);
    k_scan1<<<SCAN_NBLK, SCAN_BLK>>>();
    k_scan2<<<1, 512>>>();
    k_scan3<<<NB, 256>>>();
    k_scatter<<<EB, 256>>>(er, ec, ev);

    // ---- weight prep ----
    k_wsplit_all<<<gws, 256>>>(W_self1, W_nb1, W_self2, W_nb2);

    // ---- layer 1 ----
    k_gemm_fused<<<gmm, 256, SMEM_GEMM>>>(inputs, nullptr,
                             pWt1 + 0 * F * F, pWt2 + 0 * F * F,
                             pWt1 + 1 * F * F, pWt2 + 1 * F * F,
                             b1, pA, pSh, N_NODES);
    k_spmm1<<<(N_NODES * 32 + 255) / 256, 256>>>(g1w, g1b, g2w, g2b);

    // ---- softmax gates over nodes ----
    k_softmax_part<<<120, 256>>>();
    k_softmax_final<<<1, 128>>>(120);
    k_rz<<<NB, 256>>>();

    // ---- layer 2 (rows of X1 scaled by r) ----
    k_gemm_fused<<<gmm, 256, SMEM_GEMM>>>(pX1, pR,
                             pWt1 + 2 * F * F, pWt2 + 2 * F * F,
                             pWt1 + 3 * F * F, pWt2 + 3 * F * F,
                             b2, pA, pSh, N_NODES);
    k_spmm2<<<SPMM2_BLOCKS, 256>>>(out);

    // ---- head ----
    k_out<<<1, 128>>>(e2pw, e2pb, out);
}